// round 13
// baseline (speedup 1.0000x reference)
#include <cuda_runtime.h>
#include <cuda_fp16.h>
#include <cstdint>
#include <cstddef>

#define ATOMS   50000
#define EDGES   800000
#define NB      128     // n_atom_basis == n_filters
#define NG      64      // n_gauss
#define TS      4096    // filter table samples over [0, CUTOFF]
#define CUTOFFF 5.0f
#define ASTR    132     // smem stride (words) for A tiles (64 rows, fp32)
#define BS2     68      // smem stride (words) for fp16 B tiles (n-major)
#define TILEM   64      // row-tile size
#define PGRID   148     // persistent grid base (1 CTA/SM)
#define NSCB    196     // scan blocks: 196*256 >= ATOMS

// Scratch (no allocations allowed in kernel_launch)
__device__ __half2 g_tabh[(size_t)TS * NB];     // 2 MB  (value, delta) per column
__device__ __half2 g_rfh[(size_t)ATOMS * 64];   // 12.8MB r @ W_af in fp16
__device__ float   g_acc[(size_t)ATOMS * NB];   // 25.6MB segment-sum result
__device__ int     g_cnt[ATOMS];                // counts, then scatter cursor
__device__ int     g_off[ATOMS + 1];            // CSR offsets
__device__ int     g_bsum[256];                 // scan block sums
__device__ uint2   g_rec[EDGES];                // packed (src, dist-bits)

// ---------------------------------------------------------------------------
__device__ __forceinline__ uint32_t smem_u32(const void* p) {
    uint32_t a;
    asm("{ .reg .u64 t; cvta.to.shared.u64 t, %1; cvt.u32.u64 %0, t; }"
        : "=r"(a) : "l"(p));
    return a;
}

// ---------------------------------------------------------------------------
// Build packed fp16 table; also zeroes g_cnt.
__global__ void build_table_kernel(const float* __restrict__ Wdf2,
                                   const float* __restrict__ bdf2) {
    int lin = blockIdx.x * 128 + threadIdx.x;
    if (lin < ATOMS) g_cnt[lin] = 0;

    int row  = blockIdx.x * 4 + (threadIdx.x >> 5);
    int lane = threadIdx.x & 31;
    if (row >= TS) return;
    const float step  = CUTOFFF / (float)(TS - 1);
    const float width = 5.0f / 63.0f;
    const float coeff = -0.5f / (width * width);
    float d0 = (float)row * step;
    float d1 = d0 + step;
    float4 a0 = reinterpret_cast<const float4*>(bdf2)[lane];
    float4 a1 = a0;
    #pragma unroll 8
    for (int k = 0; k < NG; k++) {
        float off = (float)k * (5.0f / 63.0f);
        float e0 = d0 - off, e1 = d1 - off;
        float g0 = __expf(coeff * e0 * e0);
        float g1 = __expf(coeff * e1 * e1);
        float4 w = reinterpret_cast<const float4*>(Wdf2 + k * NB)[lane];
        a0.x += g0 * w.x; a0.y += g0 * w.y; a0.z += g0 * w.z; a0.w += g0 * w.w;
        a1.x += g1 * w.x; a1.y += g1 * w.y; a1.z += g1 * w.z; a1.w += g1 * w.w;
    }
    __half2 h[4];
    h[0] = __floats2half2_rn(a0.x, a1.x - a0.x);
    h[1] = __floats2half2_rn(a0.y, a1.y - a0.y);
    h[2] = __floats2half2_rn(a0.z, a1.z - a0.z);
    h[3] = __floats2half2_rn(a0.w, a1.w - a0.w);
    *reinterpret_cast<uint4*>(g_tabh + (size_t)row * NB + lane * 4) =
        *reinterpret_cast<uint4*>(h);
}

// ---------------------------------------------------------------------------
// CSR binning: histogram -> 2-kernel scan -> scatter records.
__global__ void hist_kernel(const int* __restrict__ idx, int E) {
    for (int i = blockIdx.x * blockDim.x + threadIdx.x; i < E;
         i += gridDim.x * blockDim.x) {
        int dst = __ldg(&idx[2 * i]);
        atomicAdd(&g_cnt[dst], 1);
    }
}

// Per-256-chunk totals via shfl reduce.
__global__ void scan_sums_kernel() {
    __shared__ int sm[8];
    int t = threadIdx.x, i = blockIdx.x * 256 + t;
    int v = (i < ATOMS) ? g_cnt[i] : 0;
    #pragma unroll
    for (int d = 16; d; d >>= 1) v += __shfl_down_sync(0xFFFFFFFFu, v, d);
    if ((t & 31) == 0) sm[t >> 5] = v;
    __syncthreads();
    if (t == 0) {
        int x = 0;
        #pragma unroll
        for (int w = 0; w < 8; w++) x += sm[w];
        g_bsum[blockIdx.x] = x;
    }
}

// Each block: scan the (<=256) block sums redundantly, take own prefix,
// scan its chunk, write offsets + scatter cursor.
__global__ void scan_apply_kernel(int E) {
    __shared__ int sb[256];
    __shared__ int sm[256];
    int t = threadIdx.x, b = blockIdx.x;
    int i = b * 256 + t;

    int bv = (t < NSCB) ? g_bsum[t] : 0;
    sb[t] = bv; __syncthreads();
    #pragma unroll
    for (int d = 1; d < 256; d <<= 1) {
        int x = (t >= d) ? sb[t - d] : 0;
        __syncthreads();
        sb[t] += x;
        __syncthreads();
    }
    int block_off = (b > 0) ? sb[b - 1] : 0;

    int v = (i < ATOMS) ? g_cnt[i] : 0;
    sm[t] = v; __syncthreads();
    #pragma unroll
    for (int d = 1; d < 256; d <<= 1) {
        int x = (t >= d) ? sm[t - d] : 0;
        __syncthreads();
        sm[t] += x;
        __syncthreads();
    }
    if (i < ATOMS) {
        int o = sm[t] - v + block_off;
        g_off[i] = o;
        g_cnt[i] = o;
    }
    if (b == 0 && t == 0) g_off[ATOMS] = E;
}

__global__ void scatter_kernel(const float* __restrict__ dist,
                               const int* __restrict__ idx, int E) {
    for (int i = blockIdx.x * blockDim.x + threadIdx.x; i < E;
         i += gridDim.x * blockDim.x) {
        int2 de = *reinterpret_cast<const int2*>(idx + 2 * (size_t)i);
        float d = __ldg(&dist[i]);
        int pos = atomicAdd(&g_cnt[de.x], 1);
        g_rec[pos] = make_uint2((uint32_t)de.y, __float_as_uint(d));
    }
}

// ---------------------------------------------------------------------------
// Gather: warp per atom; walk its edge list, accumulate in registers,
// one plain store. 2 records in flight (R10-validated).
__device__ __forceinline__ void edge_acc(int lane, uint2 rec, float4& acc) {
    const float scale = (float)(TS - 1) / CUTOFFF;
    float d = __uint_as_float(rec.y);
    float pos = d * scale;
    int i = (int)pos;
    i = (i < 0) ? 0 : ((i > TS - 2) ? TS - 2 : i);
    float f = pos - (float)i;
    uint4 t = __ldg(reinterpret_cast<const uint4*>(
        g_tabh + (size_t)i * NB + lane * 4));
    uint2 rr = __ldg(reinterpret_cast<const uint2*>(
        g_rfh + (size_t)rec.x * 64 + lane * 2));
    const __half2* h = reinterpret_cast<const __half2*>(&t);
    const __half2* rh = reinterpret_cast<const __half2*>(&rr);
    float2 p0 = __half22float2(h[0]);
    float2 p1 = __half22float2(h[1]);
    float2 p2 = __half22float2(h[2]);
    float2 p3 = __half22float2(h[3]);
    float2 r0 = __half22float2(rh[0]);
    float2 r1 = __half22float2(rh[1]);
    acc.x = fmaf(fmaf(f, p0.y, p0.x), r0.x, acc.x);
    acc.y = fmaf(fmaf(f, p1.y, p1.x), r0.y, acc.y);
    acc.z = fmaf(fmaf(f, p2.y, p2.x), r1.x, acc.z);
    acc.w = fmaf(fmaf(f, p3.y, p3.x), r1.y, acc.w);
}

__global__ void gather_kernel() {
    int lane   = threadIdx.x & 31;
    int warp   = (blockIdx.x * blockDim.x + threadIdx.x) >> 5;
    int nwarps = (gridDim.x * blockDim.x) >> 5;
    for (int a = warp; a < ATOMS; a += nwarps) {
        int p  = __ldg(&g_off[a]);
        int pe = __ldg(&g_off[a + 1]);
        float4 acc = make_float4(0.f, 0.f, 0.f, 0.f);
        for (; p + 2 <= pe; p += 2) {
            uint2 ra = __ldg(&g_rec[p]);
            uint2 rb = __ldg(&g_rec[p + 1]);
            edge_acc(lane, ra, acc);
            edge_acc(lane, rb, acc);
        }
        if (p < pe) {
            uint2 ra = __ldg(&g_rec[p]);
            edge_acc(lane, ra, acc);
        }
        *reinterpret_cast<float4*>(g_acc + (size_t)a * NB + lane * 4) = acc;
    }
}

// ---------------------------------------------------------------------------
__device__ __forceinline__ float sspf(float x) {
    float ax = fabsf(x);
    return fmaxf(x, 0.0f) + log1pf(__expf(-ax)) - 0.69314718f;
}

__device__ __forceinline__ void mma_f16(float* c, const uint32_t* a,
                                        uint32_t b0, uint32_t b1) {
    asm volatile(
        "mma.sync.aligned.m16n8k16.row.col.f32.f16.f16.f32 "
        "{%0,%1,%2,%3}, {%4,%5,%6,%7}, {%8,%9}, {%0,%1,%2,%3};"
        : "+f"(c[0]), "+f"(c[1]), "+f"(c[2]), "+f"(c[3])
        : "r"(a[0]), "r"(a[1]), "r"(a[2]), "r"(a[3]), "r"(b0), "r"(b1));
}

__device__ __forceinline__ uint32_t packh2(float x, float y) {
    __half2 h = __floats2half2_rn(x, y);
    return *reinterpret_cast<uint32_t*>(&h);
}

// Stage W[128,128] fp32 (k-major) -> fp16 n-major smem: Bh[n][k],
// stride 2*BS2 halves per n-row (R10-validated conflict-free layout).
__device__ __forceinline__ void stage_B_h(const float* __restrict__ W,
                                          __half* Bh, int tid) {
    for (int i = tid; i < 128 * 32; i += 256) {
        int k = i >> 5, c = i & 31;
        int n0 = c * 4;
        float4 v = reinterpret_cast<const float4*>(W + k * NB)[c];
        Bh[(n0 + 0) * (2 * BS2) + k] = __float2half_rn(v.x);
        Bh[(n0 + 1) * (2 * BS2) + k] = __float2half_rn(v.y);
        Bh[(n0 + 2) * (2 * BS2) + k] = __float2half_rn(v.z);
        Bh[(n0 + 3) * (2 * BS2) + k] = __float2half_rn(v.w);
    }
}

__device__ __forceinline__ void prefetch_A(const float* __restrict__ A,
                                           uint32_t as_addr, int row0, int M,
                                           int tid) {
    for (int i = tid; i < TILEM * 32; i += 256) {
        int r = i >> 5, c4 = (i & 31) << 2;
        int row = row0 + r;
        int srow = (row < M) ? row : (M - 1);
        const float* src = A + (size_t)srow * NB + c4;
        uint32_t dst = as_addr + (uint32_t)(r * ASTR + c4) * 4u;
        uint32_t ssz = (row < M) ? 16u : 0u;
        asm volatile("cp.async.ca.shared.global [%0], [%1], 16, %2;"
                     :: "r"(dst), "l"(src), "r"(ssz) : "memory");
    }
}
#define CP_COMMIT() asm volatile("cp.async.commit_group;" ::: "memory")
#define CP_WAIT1()  asm volatile("cp.async.wait_group 1;" ::: "memory")
#define CP_WAIT0()  asm volatile("cp.async.wait_group 0;" ::: "memory")

// One 64x128x128 tile pass, fp16 m16n8k16 (R10-validated).
__device__ __forceinline__ void mma_tile_h(const uint32_t* As,
                                           const uint32_t* Bs,
                                           int wm, int wn, int g, int tig,
                                           float acc[8][4]) {
    #pragma unroll
    for (int nt = 0; nt < 8; nt++)
        #pragma unroll
        for (int j = 0; j < 4; j++) acc[nt][j] = 0.f;

    #pragma unroll
    for (int k0 = 0; k0 < 128; k0 += 16) {
        uint32_t af[4];
        int r = wm * 16;
        float2 x;
        x = *reinterpret_cast<const float2*>(&As[(r + g)     * ASTR + k0 + 2 * tig]);
        af[0] = packh2(x.x, x.y);
        x = *reinterpret_cast<const float2*>(&As[(r + g + 8) * ASTR + k0 + 2 * tig]);
        af[1] = packh2(x.x, x.y);
        x = *reinterpret_cast<const float2*>(&As[(r + g)     * ASTR + k0 + 2 * tig + 8]);
        af[2] = packh2(x.x, x.y);
        x = *reinterpret_cast<const float2*>(&As[(r + g + 8) * ASTR + k0 + 2 * tig + 8]);
        af[3] = packh2(x.x, x.y);
        #pragma unroll
        for (int nt = 0; nt < 8; nt++) {
            int n = wn * 64 + nt * 8 + g;
            uint32_t b0 = Bs[n * BS2 + (k0 >> 1) + tig];
            uint32_t b1 = Bs[n * BS2 + (k0 >> 1) + tig + 4];
            mma_f16(acc[nt], af, b0, b1);
        }
    }
}

// ---------------------------------------------------------------------------
// Persistent GEMM1: rf(fp16) = r @ W_af. 2 CTAs/SM, A double-buffered.
__global__ __launch_bounds__(256, 2)
void gemm_p_kernel(const float* __restrict__ A, const float* __restrict__ B,
                   __half2* __restrict__ C, int M, int ntiles) {
    extern __shared__ uint32_t smu[];
    uint32_t* As0 = smu;
    uint32_t* As1 = smu + TILEM * ASTR;
    uint32_t* Bs  = smu + 2 * TILEM * ASTR;
    uint32_t as_addr0 = smem_u32(As0);
    uint32_t as_addr1 = smem_u32(As1);
    int tid = threadIdx.x;

    stage_B_h(B, reinterpret_cast<__half*>(Bs), tid);

    int warp = tid >> 5, lane = tid & 31;
    int wm = warp & 3, wn = warp >> 2;
    int g = lane >> 2, tig = lane & 3;

    int t = blockIdx.x;
    int buf = 0;
    if (t < ntiles) prefetch_A(A, as_addr0, t * TILEM, M, tid);
    CP_COMMIT();

    while (t < ntiles) {
        int tn = t + gridDim.x;
        if (tn < ntiles)
            prefetch_A(A, buf ? as_addr0 : as_addr1, tn * TILEM, M, tid);
        CP_COMMIT();
        CP_WAIT1();
        __syncthreads();

        const uint32_t* Asc = buf ? As1 : As0;
        float acc[8][4];
        mma_tile_h(Asc, Bs, wm, wn, g, tig, acc);

        int row0 = t * TILEM;
        #pragma unroll
        for (int nt = 0; nt < 8; nt++) {
            int col = wn * 64 + nt * 8 + 2 * tig;
            int r1 = row0 + wm * 16 + g, r2 = r1 + 8;
            if (r1 < M)
                C[(size_t)r1 * 64 + (col >> 1)] =
                    __floats2half2_rn(acc[nt][0], acc[nt][1]);
            if (r2 < M)
                C[(size_t)r2 * 64 + (col >> 1)] =
                    __floats2half2_rn(acc[nt][2], acc[nt][3]);
        }
        __syncthreads();
        buf ^= 1;
        t = tn;
    }
}

// ---------------------------------------------------------------------------
// Persistent fused GEMM2+3: out = ssp(A@W1+b1) @ W2 + b2.
// Single A buffer -> 103.4 KB smem -> 2 CTAs/SM; co-resident CTA hides
// the A-load and sync latencies instead of the intra-CTA double buffer.
__global__ __launch_bounds__(256, 2)
void gemm23_p_kernel(const float* __restrict__ A,
                     const float* __restrict__ W1, const float* __restrict__ b1,
                     const float* __restrict__ W2, const float* __restrict__ b2,
                     float* __restrict__ C, int M, int ntiles) {
    extern __shared__ uint32_t smu[];
    uint32_t* As  = smu;
    uint32_t* B1s = smu + TILEM * ASTR;
    uint32_t* B2s = B1s + 128 * BS2;
    uint32_t as_addr = smem_u32(As);
    int tid = threadIdx.x;

    stage_B_h(W1, reinterpret_cast<__half*>(B1s), tid);
    stage_B_h(W2, reinterpret_cast<__half*>(B2s), tid);

    int warp = tid >> 5, lane = tid & 31;
    int wm = warp & 3, wn = warp >> 2;
    int g = lane >> 2, tig = lane & 3;

    for (int t = blockIdx.x; t < ntiles; t += gridDim.x) {
        prefetch_A(A, as_addr, t * TILEM, M, tid);
        CP_COMMIT();
        CP_WAIT0();
        __syncthreads();

        float acc[8][4];

        // Pass 1: mid = ssp(A @ W1 + b1)
        mma_tile_h(As, B1s, wm, wn, g, tig, acc);
        __syncthreads();   // all warps done reading raw A before overwrite

        #pragma unroll
        for (int nt = 0; nt < 8; nt++) {
            int col = wn * 64 + nt * 8 + 2 * tig;
            float2 bv = *reinterpret_cast<const float2*>(b1 + col);
            int r1 = wm * 16 + g, r2 = r1 + 8;
            As[r1 * ASTR + col]     = __float_as_uint(sspf(acc[nt][0] + bv.x));
            As[r1 * ASTR + col + 1] = __float_as_uint(sspf(acc[nt][1] + bv.y));
            As[r2 * ASTR + col]     = __float_as_uint(sspf(acc[nt][2] + bv.x));
            As[r2 * ASTR + col + 1] = __float_as_uint(sspf(acc[nt][3] + bv.y));
        }
        __syncthreads();

        // Pass 2: out = mid @ W2 + b2
        mma_tile_h(As, B2s, wm, wn, g, tig, acc);
        int row0 = t * TILEM;
        #pragma unroll
        for (int nt = 0; nt < 8; nt++) {
            int col = wn * 64 + nt * 8 + 2 * tig;
            float2 bv = *reinterpret_cast<const float2*>(b2 + col);
            int r1 = row0 + wm * 16 + g, r2 = r1 + 8;
            if (r1 < M)
                *reinterpret_cast<float2*>(C + (size_t)r1 * NB + col) =
                    make_float2(acc[nt][0] + bv.x, acc[nt][1] + bv.y);
            if (r2 < M)
                *reinterpret_cast<float2*>(C + (size_t)r2 * NB + col) =
                    make_float2(acc[nt][2] + bv.x, acc[nt][3] + bv.y);
        }
        __syncthreads();   // all reads of As done before next prefetch
    }
}

// ---------------------------------------------------------------------------
extern "C" void kernel_launch(void* const* d_in, const int* in_sizes, int n_in,
                              void* d_out, int out_size) {
    const float* r     = (const float*)d_in[0];
    const float* e     = (const float*)d_in[1];
    const int*   a     = (const int*)  d_in[2];
    // d_in[3], d_in[4] = W_df1, b_df1: dead in the reference (overwritten)
    const float* W_df2 = (const float*)d_in[5];
    const float* b_df2 = (const float*)d_in[6];
    const float* W_af  = (const float*)d_in[7];
    const float* W_d1  = (const float*)d_in[8];
    const float* b_d1  = (const float*)d_in[9];
    const float* W_d2  = (const float*)d_in[10];
    const float* b_d2  = (const float*)d_in[11];
    float* out = (float*)d_out;

    __half2* rfh;
    float*   acc;
    cudaGetSymbolAddress((void**)&rfh, g_rfh);
    cudaGetSymbolAddress((void**)&acc, g_acc);

    const int smem1  = (2 * TILEM * ASTR + 128 * BS2) * 4;      // 102400 B
    const int smem23 = (TILEM * ASTR + 2 * 128 * BS2) * 4;      // 103424 B
    cudaFuncSetAttribute(gemm_p_kernel,
                         cudaFuncAttributeMaxDynamicSharedMemorySize, smem1);
    cudaFuncSetAttribute(gemm23_p_kernel,
                         cudaFuncAttributeMaxDynamicSharedMemorySize, smem23);

    int E = in_sizes[1];            // 800000
    int M = in_sizes[0] / NB;       // 50000
    int ntiles = (M + TILEM - 1) / TILEM;   // 782

    build_table_kernel<<<TS / 4, 128>>>(W_df2, b_df2);   // + zero g_cnt
    gemm_p_kernel<<<2 * PGRID, 256, smem1>>>(r, W_af, rfh, M, ntiles);
    hist_kernel<<<1024, 256>>>(a, E);
    scan_sums_kernel<<<NSCB, 256>>>();
    scan_apply_kernel<<<NSCB, 256>>>(E);
    scatter_kernel<<<1024, 256>>>(e, a, E);
    gather_kernel<<<1024, 256>>>();
    gemm23_p_kernel<<<2 * PGRID, 256, smem23>>>(acc, W_d1, b_d1, W_d2, b_d2,
                                                out, M, ntiles);
}

// round 15
// speedup vs baseline: 1.0345x; 1.0345x over previous
#include <cuda_runtime.h>
#include <cuda_fp16.h>
#include <cstdint>
#include <cstddef>

#define ATOMS   50000
#define EDGES   800000
#define NB      128     // n_atom_basis == n_filters
#define NG      64      // n_gauss
#define TS      4096    // filter table samples over [0, CUTOFF]
#define CUTOFFF 5.0f
#define ASTR    132     // smem stride (words) for A tiles (fp32)
#define BS2     68      // smem stride (words) for fp16 B tiles (n-major)
#define TILEM   64      // row-tile size (gemm1)
#define TILEM2  128     // row-tile size (gemm23)
#define PGRID   148     // persistent grid base (1 CTA/SM)
#define NSCB    196     // scan blocks: 196*256 >= ATOMS

// Scratch (no allocations allowed in kernel_launch)
__device__ __half2 g_tabh[(size_t)TS * NB];     // 2 MB  (value, delta) per column
__device__ __half2 g_rfh[(size_t)ATOMS * 64];   // 12.8MB r @ W_af in fp16
__device__ float   g_acc[(size_t)ATOMS * NB];   // 25.6MB segment-sum result
__device__ int     g_cnt[ATOMS];                // counts, then scatter cursor
__device__ int     g_off[ATOMS + 1];            // CSR offsets
__device__ int     g_bsum[256];                 // scan block sums
__device__ uint2   g_rec[EDGES];                // packed (src, dist-bits)

// ---------------------------------------------------------------------------
__device__ __forceinline__ uint32_t smem_u32(const void* p) {
    uint32_t a;
    asm("{ .reg .u64 t; cvta.to.shared.u64 t, %1; cvt.u32.u64 %0, t; }"
        : "=r"(a) : "l"(p));
    return a;
}

// ---------------------------------------------------------------------------
// Build packed fp16 table; also zeroes g_cnt.
__global__ void build_table_kernel(const float* __restrict__ Wdf2,
                                   const float* __restrict__ bdf2) {
    int lin = blockIdx.x * 128 + threadIdx.x;
    if (lin < ATOMS) g_cnt[lin] = 0;

    int row  = blockIdx.x * 4 + (threadIdx.x >> 5);
    int lane = threadIdx.x & 31;
    if (row >= TS) return;
    const float step  = CUTOFFF / (float)(TS - 1);
    const float width = 5.0f / 63.0f;
    const float coeff = -0.5f / (width * width);
    float d0 = (float)row * step;
    float d1 = d0 + step;
    float4 a0 = reinterpret_cast<const float4*>(bdf2)[lane];
    float4 a1 = a0;
    #pragma unroll 8
    for (int k = 0; k < NG; k++) {
        float off = (float)k * (5.0f / 63.0f);
        float e0 = d0 - off, e1 = d1 - off;
        float g0 = __expf(coeff * e0 * e0);
        float g1 = __expf(coeff * e1 * e1);
        float4 w = reinterpret_cast<const float4*>(Wdf2 + k * NB)[lane];
        a0.x += g0 * w.x; a0.y += g0 * w.y; a0.z += g0 * w.z; a0.w += g0 * w.w;
        a1.x += g1 * w.x; a1.y += g1 * w.y; a1.z += g1 * w.z; a1.w += g1 * w.w;
    }
    __half2 h[4];
    h[0] = __floats2half2_rn(a0.x, a1.x - a0.x);
    h[1] = __floats2half2_rn(a0.y, a1.y - a0.y);
    h[2] = __floats2half2_rn(a0.z, a1.z - a0.z);
    h[3] = __floats2half2_rn(a0.w, a1.w - a0.w);
    *reinterpret_cast<uint4*>(g_tabh + (size_t)row * NB + lane * 4) =
        *reinterpret_cast<uint4*>(h);
}

// ---------------------------------------------------------------------------
// CSR binning: histogram -> 2-kernel scan -> scatter records.
__global__ void hist_kernel(const int* __restrict__ idx, int E) {
    for (int i = blockIdx.x * blockDim.x + threadIdx.x; i < E;
         i += gridDim.x * blockDim.x) {
        int dst = __ldg(&idx[2 * i]);
        atomicAdd(&g_cnt[dst], 1);
    }
}

// Per-256-chunk totals via shfl reduce.
__global__ void scan_sums_kernel() {
    __shared__ int sm[8];
    int t = threadIdx.x, i = blockIdx.x * 256 + t;
    int v = (i < ATOMS) ? g_cnt[i] : 0;
    #pragma unroll
    for (int d = 16; d; d >>= 1) v += __shfl_down_sync(0xFFFFFFFFu, v, d);
    if ((t & 31) == 0) sm[t >> 5] = v;
    __syncthreads();
    if (t == 0) {
        int x = 0;
        #pragma unroll
        for (int w = 0; w < 8; w++) x += sm[w];
        g_bsum[blockIdx.x] = x;
    }
}

// Each block: scan the (<=256) block sums redundantly, take own prefix,
// scan its chunk, write offsets + scatter cursor.
__global__ void scan_apply_kernel(int E) {
    __shared__ int sb[256];
    __shared__ int sm[256];
    int t = threadIdx.x, b = blockIdx.x;
    int i = b * 256 + t;

    int bv = (t < NSCB) ? g_bsum[t] : 0;
    sb[t] = bv; __syncthreads();
    #pragma unroll
    for (int d = 1; d < 256; d <<= 1) {
        int x = (t >= d) ? sb[t - d] : 0;
        __syncthreads();
        sb[t] += x;
        __syncthreads();
    }
    int block_off = (b > 0) ? sb[b - 1] : 0;

    int v = (i < ATOMS) ? g_cnt[i] : 0;
    sm[t] = v; __syncthreads();
    #pragma unroll
    for (int d = 1; d < 256; d <<= 1) {
        int x = (t >= d) ? sm[t - d] : 0;
        __syncthreads();
        sm[t] += x;
        __syncthreads();
    }
    if (i < ATOMS) {
        int o = sm[t] - v + block_off;
        g_off[i] = o;
        g_cnt[i] = o;
    }
    if (b == 0 && t == 0) g_off[ATOMS] = E;
}

__global__ void scatter_kernel(const float* __restrict__ dist,
                               const int* __restrict__ idx, int E) {
    for (int i = blockIdx.x * blockDim.x + threadIdx.x; i < E;
         i += gridDim.x * blockDim.x) {
        int2 de = *reinterpret_cast<const int2*>(idx + 2 * (size_t)i);
        float d = __ldg(&dist[i]);
        int pos = atomicAdd(&g_cnt[de.x], 1);
        g_rec[pos] = make_uint2((uint32_t)de.y, __float_as_uint(d));
    }
}

// ---------------------------------------------------------------------------
// Gather: warp per atom; walk its edge list, accumulate in registers,
// one plain store. 2 records in flight (R10-validated).
__device__ __forceinline__ void edge_acc(int lane, uint2 rec, float4& acc) {
    const float scale = (float)(TS - 1) / CUTOFFF;
    float d = __uint_as_float(rec.y);
    float pos = d * scale;
    int i = (int)pos;
    i = (i < 0) ? 0 : ((i > TS - 2) ? TS - 2 : i);
    float f = pos - (float)i;
    uint4 t = __ldg(reinterpret_cast<const uint4*>(
        g_tabh + (size_t)i * NB + lane * 4));
    uint2 rr = __ldg(reinterpret_cast<const uint2*>(
        g_rfh + (size_t)rec.x * 64 + lane * 2));
    const __half2* h = reinterpret_cast<const __half2*>(&t);
    const __half2* rh = reinterpret_cast<const __half2*>(&rr);
    float2 p0 = __half22float2(h[0]);
    float2 p1 = __half22float2(h[1]);
    float2 p2 = __half22float2(h[2]);
    float2 p3 = __half22float2(h[3]);
    float2 r0 = __half22float2(rh[0]);
    float2 r1 = __half22float2(rh[1]);
    acc.x = fmaf(fmaf(f, p0.y, p0.x), r0.x, acc.x);
    acc.y = fmaf(fmaf(f, p1.y, p1.x), r0.y, acc.y);
    acc.z = fmaf(fmaf(f, p2.y, p2.x), r1.x, acc.z);
    acc.w = fmaf(fmaf(f, p3.y, p3.x), r1.y, acc.w);
}

__global__ void gather_kernel() {
    int lane   = threadIdx.x & 31;
    int warp   = (blockIdx.x * blockDim.x + threadIdx.x) >> 5;
    int nwarps = (gridDim.x * blockDim.x) >> 5;
    for (int a = warp; a < ATOMS; a += nwarps) {
        int p  = __ldg(&g_off[a]);
        int pe = __ldg(&g_off[a + 1]);
        float4 acc = make_float4(0.f, 0.f, 0.f, 0.f);
        for (; p + 2 <= pe; p += 2) {
            uint2 ra = __ldg(&g_rec[p]);
            uint2 rb = __ldg(&g_rec[p + 1]);
            edge_acc(lane, ra, acc);
            edge_acc(lane, rb, acc);
        }
        if (p < pe) {
            uint2 ra = __ldg(&g_rec[p]);
            edge_acc(lane, ra, acc);
        }
        *reinterpret_cast<float4*>(g_acc + (size_t)a * NB + lane * 4) = acc;
    }
}

// ---------------------------------------------------------------------------
__device__ __forceinline__ float sspf(float x) {
    float ax = fabsf(x);
    return fmaxf(x, 0.0f) + log1pf(__expf(-ax)) - 0.69314718f;
}

__device__ __forceinline__ void mma_f16(float* c, const uint32_t* a,
                                        uint32_t b0, uint32_t b1) {
    asm volatile(
        "mma.sync.aligned.m16n8k16.row.col.f32.f16.f16.f32 "
        "{%0,%1,%2,%3}, {%4,%5,%6,%7}, {%8,%9}, {%0,%1,%2,%3};"
        : "+f"(c[0]), "+f"(c[1]), "+f"(c[2]), "+f"(c[3])
        : "r"(a[0]), "r"(a[1]), "r"(a[2]), "r"(a[3]), "r"(b0), "r"(b1));
}

__device__ __forceinline__ uint32_t packh2(float x, float y) {
    __half2 h = __floats2half2_rn(x, y);
    return *reinterpret_cast<uint32_t*>(&h);
}

// Stage W[128,128] fp32 (k-major) -> fp16 n-major smem: Bh[n][k],
// stride 2*BS2 halves per n-row (R10-validated conflict-free layout).
__device__ __forceinline__ void stage_B_h(const float* __restrict__ W,
                                          __half* Bh, int tid) {
    for (int i = tid; i < 128 * 32; i += 256) {
        int k = i >> 5, c = i & 31;
        int n0 = c * 4;
        float4 v = reinterpret_cast<const float4*>(W + k * NB)[c];
        Bh[(n0 + 0) * (2 * BS2) + k] = __float2half_rn(v.x);
        Bh[(n0 + 1) * (2 * BS2) + k] = __float2half_rn(v.y);
        Bh[(n0 + 2) * (2 * BS2) + k] = __float2half_rn(v.z);
        Bh[(n0 + 3) * (2 * BS2) + k] = __float2half_rn(v.w);
    }
}

// Async prefetch of NR rows of A (raw fp32), zero-fill past M.
template <int NR>
__device__ __forceinline__ void prefetch_A(const float* __restrict__ A,
                                           uint32_t as_addr, int row0, int M,
                                           int tid) {
    for (int i = tid; i < NR * 32; i += 256) {
        int r = i >> 5, c4 = (i & 31) << 2;
        int row = row0 + r;
        int srow = (row < M) ? row : (M - 1);
        const float* src = A + (size_t)srow * NB + c4;
        uint32_t dst = as_addr + (uint32_t)(r * ASTR + c4) * 4u;
        uint32_t ssz = (row < M) ? 16u : 0u;
        asm volatile("cp.async.ca.shared.global [%0], [%1], 16, %2;"
                     :: "r"(dst), "l"(src), "r"(ssz) : "memory");
    }
}
#define CP_COMMIT() asm volatile("cp.async.commit_group;" ::: "memory")
#define CP_WAIT1()  asm volatile("cp.async.wait_group 1;" ::: "memory")

// One 64x128x128 tile pass, fp16 m16n8k16 (R10-validated). gemm1 only.
__device__ __forceinline__ void mma_tile_h(const uint32_t* As,
                                           const uint32_t* Bs,
                                           int wm, int wn, int g, int tig,
                                           float acc[8][4]) {
    #pragma unroll
    for (int nt = 0; nt < 8; nt++)
        #pragma unroll
        for (int j = 0; j < 4; j++) acc[nt][j] = 0.f;

    #pragma unroll
    for (int k0 = 0; k0 < 128; k0 += 16) {
        uint32_t af[4];
        int r = wm * 16;
        float2 x;
        x = *reinterpret_cast<const float2*>(&As[(r + g)     * ASTR + k0 + 2 * tig]);
        af[0] = packh2(x.x, x.y);
        x = *reinterpret_cast<const float2*>(&As[(r + g + 8) * ASTR + k0 + 2 * tig]);
        af[1] = packh2(x.x, x.y);
        x = *reinterpret_cast<const float2*>(&As[(r + g)     * ASTR + k0 + 2 * tig + 8]);
        af[2] = packh2(x.x, x.y);
        x = *reinterpret_cast<const float2*>(&As[(r + g + 8) * ASTR + k0 + 2 * tig + 8]);
        af[3] = packh2(x.x, x.y);
        #pragma unroll
        for (int nt = 0; nt < 8; nt++) {
            int n = wn * 64 + nt * 8 + g;
            uint32_t b0 = Bs[n * BS2 + (k0 >> 1) + tig];
            uint32_t b1 = Bs[n * BS2 + (k0 >> 1) + tig + 4];
            mma_f16(acc[nt], af, b0, b1);
        }
    }
}

// 128x128x128 tile pass for gemm23: warp tile 32x64 (2 m-subtiles share each
// B fragment -> half the B-LDS per mma, 2x independent mma chains).
__device__ __forceinline__ void mma_tile_h2(const uint32_t* As,
                                            const uint32_t* Bs,
                                            int wm, int wn, int g, int tig,
                                            float acc[2][8][4]) {
    #pragma unroll
    for (int mt = 0; mt < 2; mt++)
        #pragma unroll
        for (int nt = 0; nt < 8; nt++)
            #pragma unroll
            for (int j = 0; j < 4; j++) acc[mt][nt][j] = 0.f;

    #pragma unroll
    for (int k0 = 0; k0 < 128; k0 += 16) {
        uint32_t af[2][4];
        #pragma unroll
        for (int mt = 0; mt < 2; mt++) {
            int r = wm * 32 + mt * 16;
            float2 x;
            x = *reinterpret_cast<const float2*>(&As[(r + g)     * ASTR + k0 + 2 * tig]);
            af[mt][0] = packh2(x.x, x.y);
            x = *reinterpret_cast<const float2*>(&As[(r + g + 8) * ASTR + k0 + 2 * tig]);
            af[mt][1] = packh2(x.x, x.y);
            x = *reinterpret_cast<const float2*>(&As[(r + g)     * ASTR + k0 + 2 * tig + 8]);
            af[mt][2] = packh2(x.x, x.y);
            x = *reinterpret_cast<const float2*>(&As[(r + g + 8) * ASTR + k0 + 2 * tig + 8]);
            af[mt][3] = packh2(x.x, x.y);
        }
        #pragma unroll
        for (int nt = 0; nt < 8; nt++) {
            int n = wn * 64 + nt * 8 + g;
            uint32_t b0 = Bs[n * BS2 + (k0 >> 1) + tig];
            uint32_t b1 = Bs[n * BS2 + (k0 >> 1) + tig + 4];
            mma_f16(acc[0][nt], af[0], b0, b1);
            mma_f16(acc[1][nt], af[1], b0, b1);
        }
    }
}

// ---------------------------------------------------------------------------
// Persistent GEMM1: rf(fp16) = r @ W_af. 2 CTAs/SM, A double-buffered.
__global__ __launch_bounds__(256, 2)
void gemm_p_kernel(const float* __restrict__ A, const float* __restrict__ B,
                   __half2* __restrict__ C, int M, int ntiles) {
    extern __shared__ uint32_t smu[];
    uint32_t* As0 = smu;
    uint32_t* As1 = smu + TILEM * ASTR;
    uint32_t* Bs  = smu + 2 * TILEM * ASTR;
    uint32_t as_addr0 = smem_u32(As0);
    uint32_t as_addr1 = smem_u32(As1);
    int tid = threadIdx.x;

    stage_B_h(B, reinterpret_cast<__half*>(Bs), tid);

    int warp = tid >> 5, lane = tid & 31;
    int wm = warp & 3, wn = warp >> 2;
    int g = lane >> 2, tig = lane & 3;

    int t = blockIdx.x;
    int buf = 0;
    if (t < ntiles) prefetch_A<TILEM>(A, as_addr0, t * TILEM, M, tid);
    CP_COMMIT();

    while (t < ntiles) {
        int tn = t + gridDim.x;
        if (tn < ntiles)
            prefetch_A<TILEM>(A, buf ? as_addr0 : as_addr1, tn * TILEM, M, tid);
        CP_COMMIT();
        CP_WAIT1();
        __syncthreads();

        const uint32_t* Asc = buf ? As1 : As0;
        float acc[8][4];
        mma_tile_h(Asc, Bs, wm, wn, g, tig, acc);

        int row0 = t * TILEM;
        #pragma unroll
        for (int nt = 0; nt < 8; nt++) {
            int col = wn * 64 + nt * 8 + 2 * tig;
            int r1 = row0 + wm * 16 + g, r2 = r1 + 8;
            if (r1 < M)
                C[(size_t)r1 * 64 + (col >> 1)] =
                    __floats2half2_rn(acc[nt][0], acc[nt][1]);
            if (r2 < M)
                C[(size_t)r2 * 64 + (col >> 1)] =
                    __floats2half2_rn(acc[nt][2], acc[nt][3]);
        }
        __syncthreads();
        buf ^= 1;
        t = tn;
    }
}

// ---------------------------------------------------------------------------
// Persistent fused GEMM2+3: out = ssp(A@W1+b1) @ W2 + b2.
// TILEM2=128 tiles, A double-buffered, 1 CTA/SM (204.8 KB smem).
__global__ __launch_bounds__(256, 1)
void gemm23_p_kernel(const float* __restrict__ A,
                     const float* __restrict__ W1, const float* __restrict__ b1,
                     const float* __restrict__ W2, const float* __restrict__ b2,
                     float* __restrict__ C, int M, int ntiles) {
    extern __shared__ uint32_t smu[];
    uint32_t* As0 = smu;
    uint32_t* As1 = smu + TILEM2 * ASTR;
    uint32_t* B1s = smu + 2 * TILEM2 * ASTR;
    uint32_t* B2s = B1s + 128 * BS2;
    uint32_t as_addr0 = smem_u32(As0);
    uint32_t as_addr1 = smem_u32(As1);
    int tid = threadIdx.x;

    stage_B_h(W1, reinterpret_cast<__half*>(B1s), tid);
    stage_B_h(W2, reinterpret_cast<__half*>(B2s), tid);

    int warp = tid >> 5, lane = tid & 31;
    int wm = warp & 3, wn = warp >> 2;
    int g = lane >> 2, tig = lane & 3;

    int t = blockIdx.x;
    int buf = 0;
    if (t < ntiles) prefetch_A<TILEM2>(A, as_addr0, t * TILEM2, M, tid);
    CP_COMMIT();

    while (t < ntiles) {
        int tn = t + gridDim.x;
        if (tn < ntiles)
            prefetch_A<TILEM2>(A, buf ? as_addr0 : as_addr1, tn * TILEM2, M, tid);
        CP_COMMIT();
        CP_WAIT1();
        __syncthreads();

        uint32_t* Asc = buf ? As1 : As0;
        float acc[2][8][4];

        // Pass 1: mid = ssp(A @ W1 + b1)
        mma_tile_h2(Asc, B1s, wm, wn, g, tig, acc);
        __syncthreads();   // all warps done reading raw A before overwrite

        #pragma unroll
        for (int mt = 0; mt < 2; mt++)
            #pragma unroll
            for (int nt = 0; nt < 8; nt++) {
                int col = wn * 64 + nt * 8 + 2 * tig;
                float2 bv = *reinterpret_cast<const float2*>(b1 + col);
                int r1 = wm * 32 + mt * 16 + g, r2 = r1 + 8;
                Asc[r1 * ASTR + col]     = __float_as_uint(sspf(acc[mt][nt][0] + bv.x));
                Asc[r1 * ASTR + col + 1] = __float_as_uint(sspf(acc[mt][nt][1] + bv.y));
                Asc[r2 * ASTR + col]     = __float_as_uint(sspf(acc[mt][nt][2] + bv.x));
                Asc[r2 * ASTR + col + 1] = __float_as_uint(sspf(acc[mt][nt][3] + bv.y));
            }
        __syncthreads();

        // Pass 2: out = mid @ W2 + b2
        mma_tile_h2(Asc, B2s, wm, wn, g, tig, acc);
        int row0 = t * TILEM2;
        #pragma unroll
        for (int mt = 0; mt < 2; mt++)
            #pragma unroll
            for (int nt = 0; nt < 8; nt++) {
                int col = wn * 64 + nt * 8 + 2 * tig;
                float2 bv = *reinterpret_cast<const float2*>(b2 + col);
                int r1 = row0 + wm * 32 + mt * 16 + g, r2 = r1 + 8;
                if (r1 < M)
                    *reinterpret_cast<float2*>(C + (size_t)r1 * NB + col) =
                        make_float2(acc[mt][nt][0] + bv.x, acc[mt][nt][1] + bv.y);
                if (r2 < M)
                    *reinterpret_cast<float2*>(C + (size_t)r2 * NB + col) =
                        make_float2(acc[mt][nt][2] + bv.x, acc[mt][nt][3] + bv.y);
            }
        __syncthreads();   // all reads of Asc done before it is re-prefetched
        buf ^= 1;
        t = tn;
    }
}

// ---------------------------------------------------------------------------
extern "C" void kernel_launch(void* const* d_in, const int* in_sizes, int n_in,
                              void* d_out, int out_size) {
    const float* r     = (const float*)d_in[0];
    const float* e     = (const float*)d_in[1];
    const int*   a     = (const int*)  d_in[2];
    // d_in[3], d_in[4] = W_df1, b_df1: dead in the reference (overwritten)
    const float* W_df2 = (const float*)d_in[5];
    const float* b_df2 = (const float*)d_in[6];
    const float* W_af  = (const float*)d_in[7];
    const float* W_d1  = (const float*)d_in[8];
    const float* b_d1  = (const float*)d_in[9];
    const float* W_d2  = (const float*)d_in[10];
    const float* b_d2  = (const float*)d_in[11];
    float* out = (float*)d_out;

    __half2* rfh;
    float*   acc;
    cudaGetSymbolAddress((void**)&rfh, g_rfh);
    cudaGetSymbolAddress((void**)&acc, g_acc);

    const int smem1  = (2 * TILEM * ASTR + 128 * BS2) * 4;       // 102400 B
    const int smem23 = (2 * TILEM2 * ASTR + 2 * 128 * BS2) * 4;  // 204800 B
    cudaFuncSetAttribute(gemm_p_kernel,
                         cudaFuncAttributeMaxDynamicSharedMemorySize, smem1);
    cudaFuncSetAttribute(gemm23_p_kernel,
                         cudaFuncAttributeMaxDynamicSharedMemorySize, smem23);

    int E = in_sizes[1];            // 800000
    int M = in_sizes[0] / NB;       // 50000
    int ntiles1 = (M + TILEM - 1) / TILEM;     // 782
    int ntiles2 = (M + TILEM2 - 1) / TILEM2;   // 391

    build_table_kernel<<<TS / 4, 128>>>(W_df2, b_df2);   // + zero g_cnt
    gemm_p_kernel<<<2 * PGRID, 256, smem1>>>(r, W_af, rfh, M, ntiles1);
    hist_kernel<<<1024, 256>>>(a, E);
    scan_sums_kernel<<<NSCB, 256>>>();
    scan_apply_kernel<<<NSCB, 256>>>(E);
    scatter_kernel<<<1024, 256>>>(e, a, E);
    gather_kernel<<<1024, 256>>>();
    gemm23_p_kernel<<<PGRID, 256, smem23>>>(acc, W_d1, b_d1, W_d2, b_d2,
                                            out, M, ntiles2);
}

// round 16
// speedup vs baseline: 1.0604x; 1.0250x over previous
#include <cuda_runtime.h>
#include <cuda_fp16.h>
#include <cstdint>
#include <cstddef>

#define ATOMS   50000
#define EDGES   800000
#define NB      128     // n_atom_basis == n_filters
#define NG      64      // n_gauss
#define TS      4096    // filter table samples over [0, CUTOFF]
#define CUTOFFF 5.0f
#define ASTR    132     // smem stride (words) for fp32 A tiles (gemm1)
#define AHSTR   68      // smem stride (words=half2) for fp16 A tiles (gemm23)
#define BS2     68      // smem stride (words) for fp16 B tiles (n-major)
#define TILEM   64      // row-tile size (gemm1)
#define TILEM2  128     // row-tile size (gemm23)
#define PGRID   148     // persistent grid base (1 CTA/SM)
#define NSCB    196     // scan blocks: 196*256 >= ATOMS

// Scratch (no allocations allowed in kernel_launch)
__device__ __half2 g_tabh[(size_t)TS * NB];     // 2 MB  (value, delta) per column
__device__ __half2 g_rfh[(size_t)ATOMS * 64];   // 12.8MB r @ W_af in fp16
__device__ __half2 g_acch[(size_t)ATOMS * 64];  // 12.8MB segment-sum (fp16)
__device__ int     g_cnt[ATOMS];                // counts, then scatter cursor
__device__ int     g_off[ATOMS + 1];            // CSR offsets
__device__ int     g_bsum[256];                 // scan block sums
__device__ uint2   g_rec[EDGES];                // packed (src, dist-bits)

// ---------------------------------------------------------------------------
__device__ __forceinline__ uint32_t smem_u32(const void* p) {
    uint32_t a;
    asm("{ .reg .u64 t; cvta.to.shared.u64 t, %1; cvt.u32.u64 %0, t; }"
        : "=r"(a) : "l"(p));
    return a;
}

// ---------------------------------------------------------------------------
// Build packed fp16 table; also zeroes g_cnt.
__global__ void build_table_kernel(const float* __restrict__ Wdf2,
                                   const float* __restrict__ bdf2) {
    int lin = blockIdx.x * 128 + threadIdx.x;
    if (lin < ATOMS) g_cnt[lin] = 0;

    int row  = blockIdx.x * 4 + (threadIdx.x >> 5);
    int lane = threadIdx.x & 31;
    if (row >= TS) return;
    const float step  = CUTOFFF / (float)(TS - 1);
    const float width = 5.0f / 63.0f;
    const float coeff = -0.5f / (width * width);
    float d0 = (float)row * step;
    float d1 = d0 + step;
    float4 a0 = reinterpret_cast<const float4*>(bdf2)[lane];
    float4 a1 = a0;
    #pragma unroll 8
    for (int k = 0; k < NG; k++) {
        float off = (float)k * (5.0f / 63.0f);
        float e0 = d0 - off, e1 = d1 - off;
        float g0 = __expf(coeff * e0 * e0);
        float g1 = __expf(coeff * e1 * e1);
        float4 w = reinterpret_cast<const float4*>(Wdf2 + k * NB)[lane];
        a0.x += g0 * w.x; a0.y += g0 * w.y; a0.z += g0 * w.z; a0.w += g0 * w.w;
        a1.x += g1 * w.x; a1.y += g1 * w.y; a1.z += g1 * w.z; a1.w += g1 * w.w;
    }
    __half2 h[4];
    h[0] = __floats2half2_rn(a0.x, a1.x - a0.x);
    h[1] = __floats2half2_rn(a0.y, a1.y - a0.y);
    h[2] = __floats2half2_rn(a0.z, a1.z - a0.z);
    h[3] = __floats2half2_rn(a0.w, a1.w - a0.w);
    *reinterpret_cast<uint4*>(g_tabh + (size_t)row * NB + lane * 4) =
        *reinterpret_cast<uint4*>(h);
}

// ---------------------------------------------------------------------------
// CSR binning: histogram -> 2-kernel scan -> scatter records.
__global__ void hist_kernel(const int* __restrict__ idx, int E) {
    for (int i = blockIdx.x * blockDim.x + threadIdx.x; i < E;
         i += gridDim.x * blockDim.x) {
        int dst = __ldg(&idx[2 * i]);
        atomicAdd(&g_cnt[dst], 1);
    }
}

__global__ void scan_sums_kernel() {
    __shared__ int sm[8];
    int t = threadIdx.x, i = blockIdx.x * 256 + t;
    int v = (i < ATOMS) ? g_cnt[i] : 0;
    #pragma unroll
    for (int d = 16; d; d >>= 1) v += __shfl_down_sync(0xFFFFFFFFu, v, d);
    if ((t & 31) == 0) sm[t >> 5] = v;
    __syncthreads();
    if (t == 0) {
        int x = 0;
        #pragma unroll
        for (int w = 0; w < 8; w++) x += sm[w];
        g_bsum[blockIdx.x] = x;
    }
}

__global__ void scan_apply_kernel(int E) {
    __shared__ int sb[256];
    __shared__ int sm[256];
    int t = threadIdx.x, b = blockIdx.x;
    int i = b * 256 + t;

    int bv = (t < NSCB) ? g_bsum[t] : 0;
    sb[t] = bv; __syncthreads();
    #pragma unroll
    for (int d = 1; d < 256; d <<= 1) {
        int x = (t >= d) ? sb[t - d] : 0;
        __syncthreads();
        sb[t] += x;
        __syncthreads();
    }
    int block_off = (b > 0) ? sb[b - 1] : 0;

    int v = (i < ATOMS) ? g_cnt[i] : 0;
    sm[t] = v; __syncthreads();
    #pragma unroll
    for (int d = 1; d < 256; d <<= 1) {
        int x = (t >= d) ? sm[t - d] : 0;
        __syncthreads();
        sm[t] += x;
        __syncthreads();
    }
    if (i < ATOMS) {
        int o = sm[t] - v + block_off;
        g_off[i] = o;
        g_cnt[i] = o;
    }
    if (b == 0 && t == 0) g_off[ATOMS] = E;
}

__global__ void scatter_kernel(const float* __restrict__ dist,
                               const int* __restrict__ idx, int E) {
    for (int i = blockIdx.x * blockDim.x + threadIdx.x; i < E;
         i += gridDim.x * blockDim.x) {
        int2 de = *reinterpret_cast<const int2*>(idx + 2 * (size_t)i);
        float d = __ldg(&dist[i]);
        int pos = atomicAdd(&g_cnt[de.x], 1);
        g_rec[pos] = make_uint2((uint32_t)de.y, __float_as_uint(d));
    }
}

// ---------------------------------------------------------------------------
// Gather: warp per atom; accumulate in fp32 registers, store fp16 pairs
// (bit-identical to the fp16 conversion gemm23 would do at fragment load).
__device__ __forceinline__ void edge_acc(int lane, uint2 rec, float4& acc) {
    const float scale = (float)(TS - 1) / CUTOFFF;
    float d = __uint_as_float(rec.y);
    float pos = d * scale;
    int i = (int)pos;
    i = (i < 0) ? 0 : ((i > TS - 2) ? TS - 2 : i);
    float f = pos - (float)i;
    uint4 t = __ldg(reinterpret_cast<const uint4*>(
        g_tabh + (size_t)i * NB + lane * 4));
    uint2 rr = __ldg(reinterpret_cast<const uint2*>(
        g_rfh + (size_t)rec.x * 64 + lane * 2));
    const __half2* h = reinterpret_cast<const __half2*>(&t);
    const __half2* rh = reinterpret_cast<const __half2*>(&rr);
    float2 p0 = __half22float2(h[0]);
    float2 p1 = __half22float2(h[1]);
    float2 p2 = __half22float2(h[2]);
    float2 p3 = __half22float2(h[3]);
    float2 r0 = __half22float2(rh[0]);
    float2 r1 = __half22float2(rh[1]);
    acc.x = fmaf(fmaf(f, p0.y, p0.x), r0.x, acc.x);
    acc.y = fmaf(fmaf(f, p1.y, p1.x), r0.y, acc.y);
    acc.z = fmaf(fmaf(f, p2.y, p2.x), r1.x, acc.z);
    acc.w = fmaf(fmaf(f, p3.y, p3.x), r1.y, acc.w);
}

__global__ void gather_kernel() {
    int lane   = threadIdx.x & 31;
    int warp   = (blockIdx.x * blockDim.x + threadIdx.x) >> 5;
    int nwarps = (gridDim.x * blockDim.x) >> 5;
    for (int a = warp; a < ATOMS; a += nwarps) {
        int p  = __ldg(&g_off[a]);
        int pe = __ldg(&g_off[a + 1]);
        float4 acc = make_float4(0.f, 0.f, 0.f, 0.f);
        for (; p + 2 <= pe; p += 2) {
            uint2 ra = __ldg(&g_rec[p]);
            uint2 rb = __ldg(&g_rec[p + 1]);
            edge_acc(lane, ra, acc);
            edge_acc(lane, rb, acc);
        }
        if (p < pe) {
            uint2 ra = __ldg(&g_rec[p]);
            edge_acc(lane, ra, acc);
        }
        __half2 h0 = __floats2half2_rn(acc.x, acc.y);
        __half2 h1 = __floats2half2_rn(acc.z, acc.w);
        uint2 st;
        st.x = *reinterpret_cast<uint32_t*>(&h0);
        st.y = *reinterpret_cast<uint32_t*>(&h1);
        *reinterpret_cast<uint2*>(g_acch + (size_t)a * 64 + lane * 2) = st;
    }
}

// ---------------------------------------------------------------------------
__device__ __forceinline__ float sspf(float x) {
    float ax = fabsf(x);
    return fmaxf(x, 0.0f) + log1pf(__expf(-ax)) - 0.69314718f;
}

__device__ __forceinline__ void mma_f16(float* c, const uint32_t* a,
                                        uint32_t b0, uint32_t b1) {
    asm volatile(
        "mma.sync.aligned.m16n8k16.row.col.f32.f16.f16.f32 "
        "{%0,%1,%2,%3}, {%4,%5,%6,%7}, {%8,%9}, {%0,%1,%2,%3};"
        : "+f"(c[0]), "+f"(c[1]), "+f"(c[2]), "+f"(c[3])
        : "r"(a[0]), "r"(a[1]), "r"(a[2]), "r"(a[3]), "r"(b0), "r"(b1));
}

__device__ __forceinline__ uint32_t packh2(float x, float y) {
    __half2 h = __floats2half2_rn(x, y);
    return *reinterpret_cast<uint32_t*>(&h);
}

// Stage W[128,128] fp32 (k-major) -> fp16 n-major smem: Bh[n][k],
// stride 2*BS2 halves per n-row (R10-validated conflict-free layout).
__device__ __forceinline__ void stage_B_h(const float* __restrict__ W,
                                          __half* Bh, int tid) {
    for (int i = tid; i < 128 * 32; i += 256) {
        int k = i >> 5, c = i & 31;
        int n0 = c * 4;
        float4 v = reinterpret_cast<const float4*>(W + k * NB)[c];
        Bh[(n0 + 0) * (2 * BS2) + k] = __float2half_rn(v.x);
        Bh[(n0 + 1) * (2 * BS2) + k] = __float2half_rn(v.y);
        Bh[(n0 + 2) * (2 * BS2) + k] = __float2half_rn(v.z);
        Bh[(n0 + 3) * (2 * BS2) + k] = __float2half_rn(v.w);
    }
}

// Async prefetch of NR rows of fp32 A (gemm1), zero-fill past M.
template <int NR>
__device__ __forceinline__ void prefetch_A(const float* __restrict__ A,
                                           uint32_t as_addr, int row0, int M,
                                           int tid) {
    for (int i = tid; i < NR * 32; i += 256) {
        int r = i >> 5, c4 = (i & 31) << 2;
        int row = row0 + r;
        int srow = (row < M) ? row : (M - 1);
        const float* src = A + (size_t)srow * NB + c4;
        uint32_t dst = as_addr + (uint32_t)(r * ASTR + c4) * 4u;
        uint32_t ssz = (row < M) ? 16u : 0u;
        asm volatile("cp.async.ca.shared.global [%0], [%1], 16, %2;"
                     :: "r"(dst), "l"(src), "r"(ssz) : "memory");
    }
}

// Async prefetch of NR rows of fp16 A (gemm23): 64 half2 words per row.
template <int NR>
__device__ __forceinline__ void prefetch_Ah(const __half2* __restrict__ A,
                                            uint32_t as_addr, int row0, int M,
                                            int tid) {
    for (int i = tid; i < NR * 16; i += 256) {
        int r = i >> 4, c4 = (i & 15) << 2;      // 4 half2 words = 16 B
        int row = row0 + r;
        int srow = (row < M) ? row : (M - 1);
        const __half2* src = A + (size_t)srow * 64 + c4;
        uint32_t dst = as_addr + (uint32_t)(r * AHSTR + c4) * 4u;
        uint32_t ssz = (row < M) ? 16u : 0u;
        asm volatile("cp.async.ca.shared.global [%0], [%1], 16, %2;"
                     :: "r"(dst), "l"(src), "r"(ssz) : "memory");
    }
}
#define CP_COMMIT() asm volatile("cp.async.commit_group;" ::: "memory")
#define CP_WAIT1()  asm volatile("cp.async.wait_group 1;" ::: "memory")

// One 64x128x128 tile pass, fp32-A (cvt at load). gemm1 only.
__device__ __forceinline__ void mma_tile_h(const uint32_t* As,
                                           const uint32_t* Bs,
                                           int wm, int wn, int g, int tig,
                                           float acc[8][4]) {
    #pragma unroll
    for (int nt = 0; nt < 8; nt++)
        #pragma unroll
        for (int j = 0; j < 4; j++) acc[nt][j] = 0.f;

    #pragma unroll
    for (int k0 = 0; k0 < 128; k0 += 16) {
        uint32_t af[4];
        int r = wm * 16;
        float2 x;
        x = *reinterpret_cast<const float2*>(&As[(r + g)     * ASTR + k0 + 2 * tig]);
        af[0] = packh2(x.x, x.y);
        x = *reinterpret_cast<const float2*>(&As[(r + g + 8) * ASTR + k0 + 2 * tig]);
        af[1] = packh2(x.x, x.y);
        x = *reinterpret_cast<const float2*>(&As[(r + g)     * ASTR + k0 + 2 * tig + 8]);
        af[2] = packh2(x.x, x.y);
        x = *reinterpret_cast<const float2*>(&As[(r + g + 8) * ASTR + k0 + 2 * tig + 8]);
        af[3] = packh2(x.x, x.y);
        #pragma unroll
        for (int nt = 0; nt < 8; nt++) {
            int n = wn * 64 + nt * 8 + g;
            uint32_t b0 = Bs[n * BS2 + (k0 >> 1) + tig];
            uint32_t b1 = Bs[n * BS2 + (k0 >> 1) + tig + 4];
            mma_f16(acc[nt], af, b0, b1);
        }
    }
}

// 128x128x128 tile pass for gemm23 with fp16 A-tile (direct LDS fragments,
// no cvt in the mainloop). Warp tile 32x64.
__device__ __forceinline__ void mma_tile_h2f(const uint32_t* As,
                                             const uint32_t* Bs,
                                             int wm, int wn, int g, int tig,
                                             float acc[2][8][4]) {
    #pragma unroll
    for (int mt = 0; mt < 2; mt++)
        #pragma unroll
        for (int nt = 0; nt < 8; nt++)
            #pragma unroll
            for (int j = 0; j < 4; j++) acc[mt][nt][j] = 0.f;

    #pragma unroll
    for (int k0 = 0; k0 < 128; k0 += 16) {
        int kw = (k0 >> 1) + tig;
        uint32_t af[2][4];
        #pragma unroll
        for (int mt = 0; mt < 2; mt++) {
            int r = wm * 32 + mt * 16;
            af[mt][0] = As[(r + g)     * AHSTR + kw];
            af[mt][1] = As[(r + g + 8) * AHSTR + kw];
            af[mt][2] = As[(r + g)     * AHSTR + kw + 4];
            af[mt][3] = As[(r + g + 8) * AHSTR + kw + 4];
        }
        #pragma unroll
        for (int nt = 0; nt < 8; nt++) {
            int n = wn * 64 + nt * 8 + g;
            uint32_t b0 = Bs[n * BS2 + (k0 >> 1) + tig];
            uint32_t b1 = Bs[n * BS2 + (k0 >> 1) + tig + 4];
            mma_f16(acc[0][nt], af[0], b0, b1);
            mma_f16(acc[1][nt], af[1], b0, b1);
        }
    }
}

// ---------------------------------------------------------------------------
// Persistent GEMM1: rf(fp16) = r @ W_af. 2 CTAs/SM, A double-buffered.
__global__ __launch_bounds__(256, 2)
void gemm_p_kernel(const float* __restrict__ A, const float* __restrict__ B,
                   __half2* __restrict__ C, int M, int ntiles) {
    extern __shared__ uint32_t smu[];
    uint32_t* As0 = smu;
    uint32_t* As1 = smu + TILEM * ASTR;
    uint32_t* Bs  = smu + 2 * TILEM * ASTR;
    uint32_t as_addr0 = smem_u32(As0);
    uint32_t as_addr1 = smem_u32(As1);
    int tid = threadIdx.x;

    stage_B_h(B, reinterpret_cast<__half*>(Bs), tid);

    int warp = tid >> 5, lane = tid & 31;
    int wm = warp & 3, wn = warp >> 2;
    int g = lane >> 2, tig = lane & 3;

    int t = blockIdx.x;
    int buf = 0;
    if (t < ntiles) prefetch_A<TILEM>(A, as_addr0, t * TILEM, M, tid);
    CP_COMMIT();

    while (t < ntiles) {
        int tn = t + gridDim.x;
        if (tn < ntiles)
            prefetch_A<TILEM>(A, buf ? as_addr0 : as_addr1, tn * TILEM, M, tid);
        CP_COMMIT();
        CP_WAIT1();
        __syncthreads();

        const uint32_t* Asc = buf ? As1 : As0;
        float acc[8][4];
        mma_tile_h(Asc, Bs, wm, wn, g, tig, acc);

        int row0 = t * TILEM;
        #pragma unroll
        for (int nt = 0; nt < 8; nt++) {
            int col = wn * 64 + nt * 8 + 2 * tig;
            int r1 = row0 + wm * 16 + g, r2 = r1 + 8;
            if (r1 < M)
                C[(size_t)r1 * 64 + (col >> 1)] =
                    __floats2half2_rn(acc[nt][0], acc[nt][1]);
            if (r2 < M)
                C[(size_t)r2 * 64 + (col >> 1)] =
                    __floats2half2_rn(acc[nt][2], acc[nt][3]);
        }
        __syncthreads();
        buf ^= 1;
        t = tn;
    }
}

// ---------------------------------------------------------------------------
// Persistent fused GEMM2+3: out = ssp(A@W1+b1) @ W2 + b2.
// A is fp16 (g_acch); TILEM2=128 tiles, double-buffered, 1 CTA/SM (139 KB).
__global__ __launch_bounds__(256, 1)
void gemm23_p_kernel(const __half2* __restrict__ A,
                     const float* __restrict__ W1, const float* __restrict__ b1,
                     const float* __restrict__ W2, const float* __restrict__ b2,
                     float* __restrict__ C, int M, int ntiles) {
    extern __shared__ uint32_t smu[];
    uint32_t* As0 = smu;
    uint32_t* As1 = smu + TILEM2 * AHSTR;
    uint32_t* B1s = smu + 2 * TILEM2 * AHSTR;
    uint32_t* B2s = B1s + 128 * BS2;
    uint32_t as_addr0 = smem_u32(As0);
    uint32_t as_addr1 = smem_u32(As1);
    int tid = threadIdx.x;

    stage_B_h(W1, reinterpret_cast<__half*>(B1s), tid);
    stage_B_h(W2, reinterpret_cast<__half*>(B2s), tid);

    int warp = tid >> 5, lane = tid & 31;
    int wm = warp & 3, wn = warp >> 2;
    int g = lane >> 2, tig = lane & 3;

    int t = blockIdx.x;
    int buf = 0;
    if (t < ntiles) prefetch_Ah<TILEM2>(A, as_addr0, t * TILEM2, M, tid);
    CP_COMMIT();

    while (t < ntiles) {
        int tn = t + gridDim.x;
        if (tn < ntiles)
            prefetch_Ah<TILEM2>(A, buf ? as_addr0 : as_addr1, tn * TILEM2, M, tid);
        CP_COMMIT();
        CP_WAIT1();
        __syncthreads();

        uint32_t* Asc = buf ? As1 : As0;
        float acc[2][8][4];

        // Pass 1: mid = ssp(A @ W1 + b1)
        mma_tile_h2f(Asc, B1s, wm, wn, g, tig, acc);
        __syncthreads();   // all warps done reading A before overwrite

        #pragma unroll
        for (int mt = 0; mt < 2; mt++)
            #pragma unroll
            for (int nt = 0; nt < 8; nt++) {
                int col = wn * 64 + nt * 8 + 2 * tig;
                float2 bv = *reinterpret_cast<const float2*>(b1 + col);
                int r1 = wm * 32 + mt * 16 + g, r2 = r1 + 8;
                int cw = col >> 1;
                Asc[r1 * AHSTR + cw] = packh2(sspf(acc[mt][nt][0] + bv.x),
                                              sspf(acc[mt][nt][1] + bv.y));
                Asc[r2 * AHSTR + cw] = packh2(sspf(acc[mt][nt][2] + bv.x),
                                              sspf(acc[mt][nt][3] + bv.y));
            }
        __syncthreads();

        // Pass 2: out = mid @ W2 + b2
        mma_tile_h2f(Asc, B2s, wm, wn, g, tig, acc);
        int row0 = t * TILEM2;
        #pragma unroll
        for (int mt = 0; mt < 2; mt++)
            #pragma unroll
            for (int nt = 0; nt < 8; nt++) {
                int col = wn * 64 + nt * 8 + 2 * tig;
                float2 bv = *reinterpret_cast<const float2*>(b2 + col);
                int r1 = row0 + wm * 32 + mt * 16 + g, r2 = r1 + 8;
                if (r1 < M)
                    *reinterpret_cast<float2*>(C + (size_t)r1 * NB + col) =
                        make_float2(acc[mt][nt][0] + bv.x, acc[mt][nt][1] + bv.y);
                if (r2 < M)
                    *reinterpret_cast<float2*>(C + (size_t)r2 * NB + col) =
                        make_float2(acc[mt][nt][2] + bv.x, acc[mt][nt][3] + bv.y);
            }
        __syncthreads();   // all reads of Asc done before it is re-prefetched
        buf ^= 1;
        t = tn;
    }
}

// ---------------------------------------------------------------------------
extern "C" void kernel_launch(void* const* d_in, const int* in_sizes, int n_in,
                              void* d_out, int out_size) {
    const float* r     = (const float*)d_in[0];
    const float* e     = (const float*)d_in[1];
    const int*   a     = (const int*)  d_in[2];
    // d_in[3], d_in[4] = W_df1, b_df1: dead in the reference (overwritten)
    const float* W_df2 = (const float*)d_in[5];
    const float* b_df2 = (const float*)d_in[6];
    const float* W_af  = (const float*)d_in[7];
    const float* W_d1  = (const float*)d_in[8];
    const float* b_d1  = (const float*)d_in[9];
    const float* W_d2  = (const float*)d_in[10];
    const float* b_d2  = (const float*)d_in[11];
    float* out = (float*)d_out;

    __half2 *rfh, *acch;
    cudaGetSymbolAddress((void**)&rfh,  g_rfh);
    cudaGetSymbolAddress((void**)&acch, g_acch);

    const int smem1  = (2 * TILEM * ASTR + 128 * BS2) * 4;        // 102400 B
    const int smem23 = (2 * TILEM2 * AHSTR + 2 * 128 * BS2) * 4;  // 139264 B
    cudaFuncSetAttribute(gemm_p_kernel,
                         cudaFuncAttributeMaxDynamicSharedMemorySize, smem1);
    cudaFuncSetAttribute(gemm23_p_kernel,
                         cudaFuncAttributeMaxDynamicSharedMemorySize, smem23);

    int E = in_sizes[1];            // 800000
    int M = in_sizes[0] / NB;       // 50000
    int ntiles1 = (M + TILEM - 1) / TILEM;     // 782
    int ntiles2 = (M + TILEM2 - 1) / TILEM2;   // 391

    build_table_kernel<<<TS / 4, 128>>>(W_df2, b_df2);   // + zero g_cnt
    gemm_p_kernel<<<2 * PGRID, 256, smem1>>>(r, W_af, rfh, M, ntiles1);
    hist_kernel<<<1024, 256>>>(a, E);
    scan_sums_kernel<<<NSCB, 256>>>();
    scan_apply_kernel<<<NSCB, 256>>>(E);
    scatter_kernel<<<1024, 256>>>(e, a, E);
    gather_kernel<<<1024, 256>>>();
    gemm23_p_kernel<<<PGRID, 256, smem23>>>(acch, W_d1, b_d1, W_d2, b_d2,
                                            out, M, ntiles2);
}

// round 17
// speedup vs baseline: 1.1166x; 1.0531x over previous
#include <cuda_runtime.h>
#include <cuda_fp16.h>
#include <cstdint>
#include <cstddef>

#define ATOMS   50000
#define EDGES   800000
#define NB      128     // n_atom_basis == n_filters
#define NG      64      // n_gauss
#define TS      4096    // filter table samples over [0, CUTOFF]
#define CUTOFFF 5.0f
#define ASTR    132     // smem stride (words) for fp32 A tiles (gemm1)
#define AHSTR   68      // smem stride (words=half2) for fp16 A tiles (gemm23)
#define BS2     68      // smem stride (words) for fp16 B tiles (n-major)
#define TILEM   64      // row-tile size (gemm1)
#define TILEM2  128     // row-tile size (gemm23)
#define PGRID   148     // persistent grid base (1 CTA/SM)
#define NSCB    196     // scan blocks: 196*256 >= ATOMS

// Scratch (no allocations allowed in kernel_launch)
__device__ __half2 g_tabh[(size_t)TS * NB];     // 2 MB  (value, delta) per column
__device__ __half2 g_rfh[(size_t)ATOMS * 64];   // 12.8MB r @ W_af in fp16
__device__ __half2 g_acch[(size_t)ATOMS * 64];  // 12.8MB segment-sum (fp16)
__device__ int     g_cnt[ATOMS];                // counts, then scatter cursor
__device__ int     g_off[ATOMS + 1];            // CSR offsets
__device__ int     g_bsum[256];                 // scan block sums
__device__ uint2   g_rec[EDGES];                // packed (src, dist-bits)

// Side stream + fork/join events, created once at static-init time
// (host-side resources only; no device allocation inside kernel_launch).
static cudaStream_t g_s1;
static cudaEvent_t  g_evFork, g_evJoin;
namespace {
struct StreamInit {
    StreamInit() {
        cudaStreamCreateWithFlags(&g_s1, cudaStreamNonBlocking);
        cudaEventCreateWithFlags(&g_evFork, cudaEventDisableTiming);
        cudaEventCreateWithFlags(&g_evJoin, cudaEventDisableTiming);
    }
};
static StreamInit g_streamInit;
}

// ---------------------------------------------------------------------------
__device__ __forceinline__ uint32_t smem_u32(const void* p) {
    uint32_t a;
    asm("{ .reg .u64 t; cvta.to.shared.u64 t, %1; cvt.u32.u64 %0, t; }"
        : "=r"(a) : "l"(p));
    return a;
}

// ---------------------------------------------------------------------------
__global__ void zero_cnt_kernel() {
    int i = blockIdx.x * blockDim.x + threadIdx.x;
    if (i < ATOMS) g_cnt[i] = 0;
}

// ---------------------------------------------------------------------------
// Build packed fp16 table: tabh[i][c] = (W(d_i)[c], W(d_{i+1})[c]-W(d_i)[c])
__global__ void build_table_kernel(const float* __restrict__ Wdf2,
                                   const float* __restrict__ bdf2) {
    int row  = blockIdx.x * 4 + (threadIdx.x >> 5);
    int lane = threadIdx.x & 31;
    if (row >= TS) return;
    const float step  = CUTOFFF / (float)(TS - 1);
    const float width = 5.0f / 63.0f;
    const float coeff = -0.5f / (width * width);
    float d0 = (float)row * step;
    float d1 = d0 + step;
    float4 a0 = reinterpret_cast<const float4*>(bdf2)[lane];
    float4 a1 = a0;
    #pragma unroll 8
    for (int k = 0; k < NG; k++) {
        float off = (float)k * (5.0f / 63.0f);
        float e0 = d0 - off, e1 = d1 - off;
        float g0 = __expf(coeff * e0 * e0);
        float g1 = __expf(coeff * e1 * e1);
        float4 w = reinterpret_cast<const float4*>(Wdf2 + k * NB)[lane];
        a0.x += g0 * w.x; a0.y += g0 * w.y; a0.z += g0 * w.z; a0.w += g0 * w.w;
        a1.x += g1 * w.x; a1.y += g1 * w.y; a1.z += g1 * w.z; a1.w += g1 * w.w;
    }
    __half2 h[4];
    h[0] = __floats2half2_rn(a0.x, a1.x - a0.x);
    h[1] = __floats2half2_rn(a0.y, a1.y - a0.y);
    h[2] = __floats2half2_rn(a0.z, a1.z - a0.z);
    h[3] = __floats2half2_rn(a0.w, a1.w - a0.w);
    *reinterpret_cast<uint4*>(g_tabh + (size_t)row * NB + lane * 4) =
        *reinterpret_cast<uint4*>(h);
}

// ---------------------------------------------------------------------------
// CSR binning: histogram -> 2-kernel scan -> scatter records.
__global__ void hist_kernel(const int* __restrict__ idx, int E) {
    for (int i = blockIdx.x * blockDim.x + threadIdx.x; i < E;
         i += gridDim.x * blockDim.x) {
        int dst = __ldg(&idx[2 * i]);
        atomicAdd(&g_cnt[dst], 1);
    }
}

__global__ void scan_sums_kernel() {
    __shared__ int sm[8];
    int t = threadIdx.x, i = blockIdx.x * 256 + t;
    int v = (i < ATOMS) ? g_cnt[i] : 0;
    #pragma unroll
    for (int d = 16; d; d >>= 1) v += __shfl_down_sync(0xFFFFFFFFu, v, d);
    if ((t & 31) == 0) sm[t >> 5] = v;
    __syncthreads();
    if (t == 0) {
        int x = 0;
        #pragma unroll
        for (int w = 0; w < 8; w++) x += sm[w];
        g_bsum[blockIdx.x] = x;
    }
}

__global__ void scan_apply_kernel(int E) {
    __shared__ int sb[256];
    __shared__ int sm[256];
    int t = threadIdx.x, b = blockIdx.x;
    int i = b * 256 + t;

    int bv = (t < NSCB) ? g_bsum[t] : 0;
    sb[t] = bv; __syncthreads();
    #pragma unroll
    for (int d = 1; d < 256; d <<= 1) {
        int x = (t >= d) ? sb[t - d] : 0;
        __syncthreads();
        sb[t] += x;
        __syncthreads();
    }
    int block_off = (b > 0) ? sb[b - 1] : 0;

    int v = (i < ATOMS) ? g_cnt[i] : 0;
    sm[t] = v; __syncthreads();
    #pragma unroll
    for (int d = 1; d < 256; d <<= 1) {
        int x = (t >= d) ? sm[t - d] : 0;
        __syncthreads();
        sm[t] += x;
        __syncthreads();
    }
    if (i < ATOMS) {
        int o = sm[t] - v + block_off;
        g_off[i] = o;
        g_cnt[i] = o;
    }
    if (b == 0 && t == 0) g_off[ATOMS] = E;
}

__global__ void scatter_kernel(const float* __restrict__ dist,
                               const int* __restrict__ idx, int E) {
    for (int i = blockIdx.x * blockDim.x + threadIdx.x; i < E;
         i += gridDim.x * blockDim.x) {
        int2 de = *reinterpret_cast<const int2*>(idx + 2 * (size_t)i);
        float d = __ldg(&dist[i]);
        int pos = atomicAdd(&g_cnt[de.x], 1);
        g_rec[pos] = make_uint2((uint32_t)de.y, __float_as_uint(d));
    }
}

// ---------------------------------------------------------------------------
// Gather: warp per atom; accumulate in fp32 registers, store fp16 pairs.
__device__ __forceinline__ void edge_acc(int lane, uint2 rec, float4& acc) {
    const float scale = (float)(TS - 1) / CUTOFFF;
    float d = __uint_as_float(rec.y);
    float pos = d * scale;
    int i = (int)pos;
    i = (i < 0) ? 0 : ((i > TS - 2) ? TS - 2 : i);
    float f = pos - (float)i;
    uint4 t = __ldg(reinterpret_cast<const uint4*>(
        g_tabh + (size_t)i * NB + lane * 4));
    uint2 rr = __ldg(reinterpret_cast<const uint2*>(
        g_rfh + (size_t)rec.x * 64 + lane * 2));
    const __half2* h = reinterpret_cast<const __half2*>(&t);
    const __half2* rh = reinterpret_cast<const __half2*>(&rr);
    float2 p0 = __half22float2(h[0]);
    float2 p1 = __half22float2(h[1]);
    float2 p2 = __half22float2(h[2]);
    float2 p3 = __half22float2(h[3]);
    float2 r0 = __half22float2(rh[0]);
    float2 r1 = __half22float2(rh[1]);
    acc.x = fmaf(fmaf(f, p0.y, p0.x), r0.x, acc.x);
    acc.y = fmaf(fmaf(f, p1.y, p1.x), r0.y, acc.y);
    acc.z = fmaf(fmaf(f, p2.y, p2.x), r1.x, acc.z);
    acc.w = fmaf(fmaf(f, p3.y, p3.x), r1.y, acc.w);
}

__global__ void gather_kernel() {
    int lane   = threadIdx.x & 31;
    int warp   = (blockIdx.x * blockDim.x + threadIdx.x) >> 5;
    int nwarps = (gridDim.x * blockDim.x) >> 5;
    for (int a = warp; a < ATOMS; a += nwarps) {
        int p  = __ldg(&g_off[a]);
        int pe = __ldg(&g_off[a + 1]);
        float4 acc = make_float4(0.f, 0.f, 0.f, 0.f);
        for (; p + 2 <= pe; p += 2) {
            uint2 ra = __ldg(&g_rec[p]);
            uint2 rb = __ldg(&g_rec[p + 1]);
            edge_acc(lane, ra, acc);
            edge_acc(lane, rb, acc);
        }
        if (p < pe) {
            uint2 ra = __ldg(&g_rec[p]);
            edge_acc(lane, ra, acc);
        }
        __half2 h0 = __floats2half2_rn(acc.x, acc.y);
        __half2 h1 = __floats2half2_rn(acc.z, acc.w);
        uint2 st;
        st.x = *reinterpret_cast<uint32_t*>(&h0);
        st.y = *reinterpret_cast<uint32_t*>(&h1);
        *reinterpret_cast<uint2*>(g_acch + (size_t)a * 64 + lane * 2) = st;
    }
}

// ---------------------------------------------------------------------------
__device__ __forceinline__ float sspf(float x) {
    float ax = fabsf(x);
    return fmaxf(x, 0.0f) + log1pf(__expf(-ax)) - 0.69314718f;
}

__device__ __forceinline__ void mma_f16(float* c, const uint32_t* a,
                                        uint32_t b0, uint32_t b1) {
    asm volatile(
        "mma.sync.aligned.m16n8k16.row.col.f32.f16.f16.f32 "
        "{%0,%1,%2,%3}, {%4,%5,%6,%7}, {%8,%9}, {%0,%1,%2,%3};"
        : "+f"(c[0]), "+f"(c[1]), "+f"(c[2]), "+f"(c[3])
        : "r"(a[0]), "r"(a[1]), "r"(a[2]), "r"(a[3]), "r"(b0), "r"(b1));
}

__device__ __forceinline__ uint32_t packh2(float x, float y) {
    __half2 h = __floats2half2_rn(x, y);
    return *reinterpret_cast<uint32_t*>(&h);
}

// Stage W[128,128] fp32 (k-major) -> fp16 n-major smem: Bh[n][k].
__device__ __forceinline__ void stage_B_h(const float* __restrict__ W,
                                          __half* Bh, int tid) {
    for (int i = tid; i < 128 * 32; i += 256) {
        int k = i >> 5, c = i & 31;
        int n0 = c * 4;
        float4 v = reinterpret_cast<const float4*>(W + k * NB)[c];
        Bh[(n0 + 0) * (2 * BS2) + k] = __float2half_rn(v.x);
        Bh[(n0 + 1) * (2 * BS2) + k] = __float2half_rn(v.y);
        Bh[(n0 + 2) * (2 * BS2) + k] = __float2half_rn(v.z);
        Bh[(n0 + 3) * (2 * BS2) + k] = __float2half_rn(v.w);
    }
}

// Async prefetch of NR rows of fp32 A (gemm1), zero-fill past M.
template <int NR>
__device__ __forceinline__ void prefetch_A(const float* __restrict__ A,
                                           uint32_t as_addr, int row0, int M,
                                           int tid) {
    for (int i = tid; i < NR * 32; i += 256) {
        int r = i >> 5, c4 = (i & 31) << 2;
        int row = row0 + r;
        int srow = (row < M) ? row : (M - 1);
        const float* src = A + (size_t)srow * NB + c4;
        uint32_t dst = as_addr + (uint32_t)(r * ASTR + c4) * 4u;
        uint32_t ssz = (row < M) ? 16u : 0u;
        asm volatile("cp.async.ca.shared.global [%0], [%1], 16, %2;"
                     :: "r"(dst), "l"(src), "r"(ssz) : "memory");
    }
}

// Async prefetch of NR rows of fp16 A (gemm23): 64 half2 words per row.
template <int NR>
__device__ __forceinline__ void prefetch_Ah(const __half2* __restrict__ A,
                                            uint32_t as_addr, int row0, int M,
                                            int tid) {
    for (int i = tid; i < NR * 16; i += 256) {
        int r = i >> 4, c4 = (i & 15) << 2;      // 4 half2 words = 16 B
        int row = row0 + r;
        int srow = (row < M) ? row : (M - 1);
        const __half2* src = A + (size_t)srow * 64 + c4;
        uint32_t dst = as_addr + (uint32_t)(r * AHSTR + c4) * 4u;
        uint32_t ssz = (row < M) ? 16u : 0u;
        asm volatile("cp.async.ca.shared.global [%0], [%1], 16, %2;"
                     :: "r"(dst), "l"(src), "r"(ssz) : "memory");
    }
}
#define CP_COMMIT() asm volatile("cp.async.commit_group;" ::: "memory")
#define CP_WAIT1()  asm volatile("cp.async.wait_group 1;" ::: "memory")

// One 64x128x128 tile pass, fp32-A (cvt at load). gemm1 only.
__device__ __forceinline__ void mma_tile_h(const uint32_t* As,
                                           const uint32_t* Bs,
                                           int wm, int wn, int g, int tig,
                                           float acc[8][4]) {
    #pragma unroll
    for (int nt = 0; nt < 8; nt++)
        #pragma unroll
        for (int j = 0; j < 4; j++) acc[nt][j] = 0.f;

    #pragma unroll
    for (int k0 = 0; k0 < 128; k0 += 16) {
        uint32_t af[4];
        int r = wm * 16;
        float2 x;
        x = *reinterpret_cast<const float2*>(&As[(r + g)     * ASTR + k0 + 2 * tig]);
        af[0] = packh2(x.x, x.y);
        x = *reinterpret_cast<const float2*>(&As[(r + g + 8) * ASTR + k0 + 2 * tig]);
        af[1] = packh2(x.x, x.y);
        x = *reinterpret_cast<const float2*>(&As[(r + g)     * ASTR + k0 + 2 * tig + 8]);
        af[2] = packh2(x.x, x.y);
        x = *reinterpret_cast<const float2*>(&As[(r + g + 8) * ASTR + k0 + 2 * tig + 8]);
        af[3] = packh2(x.x, x.y);
        #pragma unroll
        for (int nt = 0; nt < 8; nt++) {
            int n = wn * 64 + nt * 8 + g;
            uint32_t b0 = Bs[n * BS2 + (k0 >> 1) + tig];
            uint32_t b1 = Bs[n * BS2 + (k0 >> 1) + tig + 4];
            mma_f16(acc[nt], af, b0, b1);
        }
    }
}

// 128x128x128 tile pass for gemm23 with fp16 A-tile. Warp tile 32x64.
__device__ __forceinline__ void mma_tile_h2f(const uint32_t* As,
                                             const uint32_t* Bs,
                                             int wm, int wn, int g, int tig,
                                             float acc[2][8][4]) {
    #pragma unroll
    for (int mt = 0; mt < 2; mt++)
        #pragma unroll
        for (int nt = 0; nt < 8; nt++)
            #pragma unroll
            for (int j = 0; j < 4; j++) acc[mt][nt][j] = 0.f;

    #pragma unroll
    for (int k0 = 0; k0 < 128; k0 += 16) {
        int kw = (k0 >> 1) + tig;
        uint32_t af[2][4];
        #pragma unroll
        for (int mt = 0; mt < 2; mt++) {
            int r = wm * 32 + mt * 16;
            af[mt][0] = As[(r + g)     * AHSTR + kw];
            af[mt][1] = As[(r + g + 8) * AHSTR + kw];
            af[mt][2] = As[(r + g)     * AHSTR + kw + 4];
            af[mt][3] = As[(r + g + 8) * AHSTR + kw + 4];
        }
        #pragma unroll
        for (int nt = 0; nt < 8; nt++) {
            int n = wn * 64 + nt * 8 + g;
            uint32_t b0 = Bs[n * BS2 + (k0 >> 1) + tig];
            uint32_t b1 = Bs[n * BS2 + (k0 >> 1) + tig + 4];
            mma_f16(acc[0][nt], af[0], b0, b1);
            mma_f16(acc[1][nt], af[1], b0, b1);
        }
    }
}

// ---------------------------------------------------------------------------
// Persistent GEMM1: rf(fp16) = r @ W_af. 2 CTAs/SM, A double-buffered.
__global__ __launch_bounds__(256, 2)
void gemm_p_kernel(const float* __restrict__ A, const float* __restrict__ B,
                   __half2* __restrict__ C, int M, int ntiles) {
    extern __shared__ uint32_t smu[];
    uint32_t* As0 = smu;
    uint32_t* As1 = smu + TILEM * ASTR;
    uint32_t* Bs  = smu + 2 * TILEM * ASTR;
    uint32_t as_addr0 = smem_u32(As0);
    uint32_t as_addr1 = smem_u32(As1);
    int tid = threadIdx.x;

    stage_B_h(B, reinterpret_cast<__half*>(Bs), tid);

    int warp = tid >> 5, lane = tid & 31;
    int wm = warp & 3, wn = warp >> 2;
    int g = lane >> 2, tig = lane & 3;

    int t = blockIdx.x;
    int buf = 0;
    if (t < ntiles) prefetch_A<TILEM>(A, as_addr0, t * TILEM, M, tid);
    CP_COMMIT();

    while (t < ntiles) {
        int tn = t + gridDim.x;
        if (tn < ntiles)
            prefetch_A<TILEM>(A, buf ? as_addr0 : as_addr1, tn * TILEM, M, tid);
        CP_COMMIT();
        CP_WAIT1();
        __syncthreads();

        const uint32_t* Asc = buf ? As1 : As0;
        float acc[8][4];
        mma_tile_h(Asc, Bs, wm, wn, g, tig, acc);

        int row0 = t * TILEM;
        #pragma unroll
        for (int nt = 0; nt < 8; nt++) {
            int col = wn * 64 + nt * 8 + 2 * tig;
            int r1 = row0 + wm * 16 + g, r2 = r1 + 8;
            if (r1 < M)
                C[(size_t)r1 * 64 + (col >> 1)] =
                    __floats2half2_rn(acc[nt][0], acc[nt][1]);
            if (r2 < M)
                C[(size_t)r2 * 64 + (col >> 1)] =
                    __floats2half2_rn(acc[nt][2], acc[nt][3]);
        }
        __syncthreads();
        buf ^= 1;
        t = tn;
    }
}

// ---------------------------------------------------------------------------
// Persistent fused GEMM2+3: out = ssp(A@W1+b1) @ W2 + b2.
// A is fp16 (g_acch); TILEM2=128 tiles, double-buffered, 1 CTA/SM (139 KB).
__global__ __launch_bounds__(256, 1)
void gemm23_p_kernel(const __half2* __restrict__ A,
                     const float* __restrict__ W1, const float* __restrict__ b1,
                     const float* __restrict__ W2, const float* __restrict__ b2,
                     float* __restrict__ C, int M, int ntiles) {
    extern __shared__ uint32_t smu[];
    uint32_t* As0 = smu;
    uint32_t* As1 = smu + TILEM2 * AHSTR;
    uint32_t* B1s = smu + 2 * TILEM2 * AHSTR;
    uint32_t* B2s = B1s + 128 * BS2;
    uint32_t as_addr0 = smem_u32(As0);
    uint32_t as_addr1 = smem_u32(As1);
    int tid = threadIdx.x;

    stage_B_h(W1, reinterpret_cast<__half*>(B1s), tid);
    stage_B_h(W2, reinterpret_cast<__half*>(B2s), tid);

    int warp = tid >> 5, lane = tid & 31;
    int wm = warp & 3, wn = warp >> 2;
    int g = lane >> 2, tig = lane & 3;

    int t = blockIdx.x;
    int buf = 0;
    if (t < ntiles) prefetch_Ah<TILEM2>(A, as_addr0, t * TILEM2, M, tid);
    CP_COMMIT();

    while (t < ntiles) {
        int tn = t + gridDim.x;
        if (tn < ntiles)
            prefetch_Ah<TILEM2>(A, buf ? as_addr0 : as_addr1, tn * TILEM2, M, tid);
        CP_COMMIT();
        CP_WAIT1();
        __syncthreads();

        uint32_t* Asc = buf ? As1 : As0;
        float acc[2][8][4];

        // Pass 1: mid = ssp(A @ W1 + b1)
        mma_tile_h2f(Asc, B1s, wm, wn, g, tig, acc);
        __syncthreads();   // all warps done reading A before overwrite

        #pragma unroll
        for (int mt = 0; mt < 2; mt++)
            #pragma unroll
            for (int nt = 0; nt < 8; nt++) {
                int col = wn * 64 + nt * 8 + 2 * tig;
                float2 bv = *reinterpret_cast<const float2*>(b1 + col);
                int r1 = wm * 32 + mt * 16 + g, r2 = r1 + 8;
                int cw = col >> 1;
                Asc[r1 * AHSTR + cw] = packh2(sspf(acc[mt][nt][0] + bv.x),
                                              sspf(acc[mt][nt][1] + bv.y));
                Asc[r2 * AHSTR + cw] = packh2(sspf(acc[mt][nt][2] + bv.x),
                                              sspf(acc[mt][nt][3] + bv.y));
            }
        __syncthreads();

        // Pass 2: out = mid @ W2 + b2
        mma_tile_h2f(Asc, B2s, wm, wn, g, tig, acc);
        int row0 = t * TILEM2;
        #pragma unroll
        for (int mt = 0; mt < 2; mt++)
            #pragma unroll
            for (int nt = 0; nt < 8; nt++) {
                int col = wn * 64 + nt * 8 + 2 * tig;
                float2 bv = *reinterpret_cast<const float2*>(b2 + col);
                int r1 = row0 + wm * 32 + mt * 16 + g, r2 = r1 + 8;
                if (r1 < M)
                    *reinterpret_cast<float2*>(C + (size_t)r1 * NB + col) =
                        make_float2(acc[mt][nt][0] + bv.x, acc[mt][nt][1] + bv.y);
                if (r2 < M)
                    *reinterpret_cast<float2*>(C + (size_t)r2 * NB + col) =
                        make_float2(acc[mt][nt][2] + bv.x, acc[mt][nt][3] + bv.y);
            }
        __syncthreads();   // all reads of Asc done before it is re-prefetched
        buf ^= 1;
        t = tn;
    }
}

// ---------------------------------------------------------------------------
extern "C" void kernel_launch(void* const* d_in, const int* in_sizes, int n_in,
                              void* d_out, int out_size) {
    const float* r     = (const float*)d_in[0];
    const float* e     = (const float*)d_in[1];
    const int*   a     = (const int*)  d_in[2];
    // d_in[3], d_in[4] = W_df1, b_df1: dead in the reference (overwritten)
    const float* W_df2 = (const float*)d_in[5];
    const float* b_df2 = (const float*)d_in[6];
    const float* W_af  = (const float*)d_in[7];
    const float* W_d1  = (const float*)d_in[8];
    const float* b_d1  = (const float*)d_in[9];
    const float* W_d2  = (const float*)d_in[10];
    const float* b_d2  = (const float*)d_in[11];
    float* out = (float*)d_out;

    __half2 *rfh, *acch;
    cudaGetSymbolAddress((void**)&rfh,  g_rfh);
    cudaGetSymbolAddress((void**)&acch, g_acch);

    const int smem1  = (2 * TILEM * ASTR + 128 * BS2) * 4;        // 102400 B
    const int smem23 = (2 * TILEM2 * AHSTR + 2 * 128 * BS2) * 4;  // 139264 B
    cudaFuncSetAttribute(gemm_p_kernel,
                         cudaFuncAttributeMaxDynamicSharedMemorySize, smem1);
    cudaFuncSetAttribute(gemm23_p_kernel,
                         cudaFuncAttributeMaxDynamicSharedMemorySize, smem23);

    int E = in_sizes[1];            // 800000
    int M = in_sizes[0] / NB;       // 50000
    int ntiles1 = (M + TILEM - 1) / TILEM;     // 782
    int ntiles2 = (M + TILEM2 - 1) / TILEM2;   // 391

    // Fork: binning chain on side stream, table+gemm1 on main stream.
    cudaEventRecord(g_evFork, 0);
    cudaStreamWaitEvent(g_s1, g_evFork, 0);

    zero_cnt_kernel<<<NSCB, 256, 0, g_s1>>>();
    hist_kernel<<<1024, 256, 0, g_s1>>>(a, E);
    scan_sums_kernel<<<NSCB, 256, 0, g_s1>>>();
    scan_apply_kernel<<<NSCB, 256, 0, g_s1>>>(E);
    scatter_kernel<<<1024, 256, 0, g_s1>>>(e, a, E);
    cudaEventRecord(g_evJoin, g_s1);

    build_table_kernel<<<TS / 4, 128>>>(W_df2, b_df2);
    gemm_p_kernel<<<2 * PGRID, 256, smem1>>>(r, W_af, rfh, M, ntiles1);

    // Join: gather needs both branches.
    cudaStreamWaitEvent(0, g_evJoin, 0);
    gather_kernel<<<1024, 256>>>();
    gemm23_p_kernel<<<PGRID, 256, smem23>>>(acch, W_d1, b_d1, W_d2, b_d2,
                                            out, M, ntiles2);
}